// round 2
// baseline (speedup 1.0000x reference)
#include <cuda_runtime.h>

#define POOL      7
#define NUM_ROIS  300
#define FH        200
#define FW        200
#define FC        512
#define FC4       (FC / 4)   // 128 float4 per pixel

// One block per (py, roi). 128 threads; thread t owns float4 channel-slot t.
// Loops over the 7 px cells with 1-deep prefetch: 8 float4 loads in flight.
__global__ __launch_bounds__(128, 8)
void roi_pool_kernel(const float4* __restrict__ feat,
                     const int*    __restrict__ rois,
                     float4*       __restrict__ out)
{
    const int py  = blockIdx.x;   // 0..6
    const int roi = blockIdx.y;   // 0..299
    const int t   = threadIdx.x;  // 0..127

    const int x0 = rois[roi * 4 + 0];
    const int y0 = rois[roi * 4 + 1];
    const int w  = rois[roi * 4 + 2];
    const int h  = rois[roi * 4 + 3];

    // Row geometry (loop-invariant)
    const float hs = (float)h / (float)POOL;
    const float sy = (float)py * hs;
    const int   y_lo = (int)floorf(sy);
    const int   y_hi = min(y_lo + 1, h - 1);
    const float fy   = sy - (float)y_lo;
    const float gy   = 1.0f - fy;

    const float4* __restrict__ rowLo = feat + (size_t)(y0 + y_lo) * FW * FC4;
    const float4* __restrict__ rowHi = feat + (size_t)(y0 + y_hi) * FW * FC4;

    // Column geometry for all 7 cells
    const float ws = (float)w / (float)POOL;
    int   xoffl[POOL], xoffh[POOL];
    float fxv[POOL];
#pragma unroll
    for (int px = 0; px < POOL; ++px) {
        const float sx  = (float)px * ws;
        const int x_lo  = (int)floorf(sx);
        const int x_hi  = min(x_lo + 1, w - 1);
        fxv[px]   = sx - (float)x_lo;
        xoffl[px] = (x0 + x_lo) * FC4 + t;
        xoffh[px] = (x0 + x_hi) * FC4 + t;
    }

    float4* __restrict__ po = out + ((size_t)roi * (POOL * POOL) + (size_t)py * POOL) * FC4 + t;

    // Prefetch cell 0
    float4 a00 = rowLo[xoffl[0]];
    float4 a01 = rowLo[xoffh[0]];
    float4 a10 = rowHi[xoffl[0]];
    float4 a11 = rowHi[xoffh[0]];

#pragma unroll
    for (int px = 0; px < POOL; ++px) {
        float4 b00, b01, b10, b11;
        if (px < POOL - 1) {               // prefetch next cell while blending
            b00 = rowLo[xoffl[px + 1]];
            b01 = rowLo[xoffh[px + 1]];
            b10 = rowHi[xoffl[px + 1]];
            b11 = rowHi[xoffh[px + 1]];
        }

        const float fx = fxv[px];
        const float gx = 1.0f - fx;

        float4 r;
        // top = v00*(1-fx) + v01*fx ; bot = v10*(1-fx) + v11*fx ; r = top*(1-fy) + bot*fy
        r.x = (a00.x * gx + a01.x * fx) * gy + (a10.x * gx + a11.x * fx) * fy;
        r.y = (a00.y * gx + a01.y * fx) * gy + (a10.y * gx + a11.y * fx) * fy;
        r.z = (a00.z * gx + a01.z * fx) * gy + (a10.z * gx + a11.z * fx) * fy;
        r.w = (a00.w * gx + a01.w * fx) * gy + (a10.w * gx + a11.w * fx) * fy;

        po[(size_t)px * FC4] = r;

        a00 = b00; a01 = b01; a10 = b10; a11 = b11;
    }
}

extern "C" void kernel_launch(void* const* d_in, const int* in_sizes, int n_in,
                              void* d_out, int out_size)
{
    const float4* feat = (const float4*)d_in[0];   // (1,200,200,512) f32
    const int*    rois = (const int*)d_in[1];      // (1,300,4) i32
    float4*       out  = (float4*)d_out;           // (1,300,7,7,512) f32

    dim3 grid(POOL, NUM_ROIS);
    roi_pool_kernel<<<grid, 128>>>(feat, rois, out);
}